// round 1
// baseline (speedup 1.0000x reference)
#include <cuda_runtime.h>

// Cost volume: out[b,d,h,w] = (1/C) * sum_c left[b,c,h,w] * right[b,c,h,w-d], 0 for w<d
// B=8, C=64, H=160, W=320, D=48.

#define BB 8
#define CC 64
#define HH 160
#define WW 320
#define DD 48

#define CK   16            // C-chunk staged in SMEM
#define PAD  52            // left zero-pad of right row (covers w-d down to -48, keeps 16B align)
#define SLS  328           // left  smem row stride (floats), mult of 4
#define SRS  376           // right smem row stride (floats), mult of 4 (320 + 52 pad + slack)
#define NT   480           // 12 d-groups (x4) * 40 w-groups (x8)

__global__ __launch_bounds__(NT) void corvol_kernel(
    const float* __restrict__ left,
    const float* __restrict__ right,
    float* __restrict__ out)
{
    __shared__ __align__(16) float sL[CK][SLS];
    __shared__ __align__(16) float sR[CK][SRS];

    const int bh = blockIdx.x;
    const int b  = bh / HH;
    const int h  = bh % HH;
    const int tid = threadIdx.x;

    const int dg = tid / 40;     // 0..11
    const int wg = tid % 40;     // 0..39
    const int d0 = dg * 4;
    const int w0 = wg * 8;

    const float* lb = left  + ((size_t)b * CC * HH + h) * WW;  // + c*HH*WW selects channel row
    const float* rb = right + ((size_t)b * CC * HH + h) * WW;

    float acc[4][8];
    #pragma unroll
    for (int di = 0; di < 4; di++)
        #pragma unroll
        for (int wi = 0; wi < 8; wi++)
            acc[di][wi] = 0.0f;

    for (int c0 = 0; c0 < CC; c0 += CK) {
        __syncthreads();   // protect smem from previous iteration's readers

        // Stage CK channel rows of left & right (float4, fully coalesced).
        #pragma unroll 2
        for (int i = tid; i < CK * (WW / 4); i += NT) {
            const int cc = i / (WW / 4);
            const int v  = (i % (WW / 4)) * 4;
            const size_t goff = (size_t)(c0 + cc) * (HH * WW) + v;
            const float4 lv = *(const float4*)(lb + goff);
            const float4 rv = *(const float4*)(rb + goff);
            *(float4*)&sL[cc][v]       = lv;
            *(float4*)&sR[cc][PAD + v] = rv;
        }
        // Zero the pad region (PAD=52 floats = 13 float4 per row).
        if (tid < CK * (PAD / 4)) {
            const int cc = tid / (PAD / 4);
            const int v  = (tid % (PAD / 4)) * 4;
            *(float4*)&sR[cc][v] = make_float4(0.f, 0.f, 0.f, 0.f);
        }
        __syncthreads();

        #pragma unroll 4
        for (int cc = 0; cc < CK; cc++) {
            float l[8];
            *(float4*)&l[0] = *(const float4*)&sL[cc][w0];
            *(float4*)&l[4] = *(const float4*)&sL[cc][w0 + 4];

            // Need right[w-d] for w in [w0,w0+7], d in [d0,d0+3]
            //   -> smem indices [w0-d0-3+PAD, w0-d0+7+PAD]; load 12 from aligned base.
            float r[12];
            const int rbase = w0 - d0 + (PAD - 4);   // multiple of 4 -> 16B aligned
            *(float4*)&r[0] = *(const float4*)&sR[cc][rbase];
            *(float4*)&r[4] = *(const float4*)&sR[cc][rbase + 4];
            *(float4*)&r[8] = *(const float4*)&sR[cc][rbase + 8];

            #pragma unroll
            for (int di = 0; di < 4; di++)
                #pragma unroll
                for (int wi = 0; wi < 8; wi++)
                    acc[di][wi] = fmaf(l[wi], r[wi - di + 4], acc[di][wi]);
        }
    }

    const float inv = 1.0f / (float)CC;
    #pragma unroll
    for (int di = 0; di < 4; di++) {
        float* op = out + (((size_t)b * DD + (d0 + di)) * HH + h) * WW + w0;
        float4 o0 = make_float4(acc[di][0] * inv, acc[di][1] * inv,
                                acc[di][2] * inv, acc[di][3] * inv);
        float4 o1 = make_float4(acc[di][4] * inv, acc[di][5] * inv,
                                acc[di][6] * inv, acc[di][7] * inv);
        *(float4*)op       = o0;
        *(float4*)(op + 4) = o1;
    }
}

extern "C" void kernel_launch(void* const* d_in, const int* in_sizes, int n_in,
                              void* d_out, int out_size)
{
    const float* left  = (const float*)d_in[0];
    const float* right = (const float*)d_in[1];
    float* out = (float*)d_out;
    corvol_kernel<<<BB * HH, NT>>>(left, right, out);
}

// round 2
// speedup vs baseline: 1.5528x; 1.5528x over previous
#include <cuda_runtime.h>

// Cost volume: out[b,d,h,w] = (1/C) * sum_c left[b,c,h,w] * right[b,c,h,w-d], 0 for w<d
// B=8, C=64, H=160, W=320, D=48.

#define BB 8
#define CC 64
#define HH 160
#define WW 320
#define DD 48

#define CK   8             // C-chunk staged in SMEM per stage
#define PAD  48            // left zero-pad of right row (covers w-d down to -48)
#define NT   240           // 6 d-groups (x8) * 40 w-groups (x8)

// Bank-conflict-free arithmetic swizzle: insert 4-float gap every 32 floats.
// Maps lane stride of 8 floats onto 8 distinct banks per 8-lane phase.
#define SW(i) ((i) + 4 * ((i) >> 5))

#define SLS  (SW(WW - 1) + 5)          // 356 physical floats per left row
#define SRS  (SW(PAD + WW - 1) + 5)    // 412 physical floats per right row

__global__ __launch_bounds__(NT, 2) void corvol_kernel(
    const float* __restrict__ left,
    const float* __restrict__ right,
    float* __restrict__ out)
{
    __shared__ __align__(16) float sL[CK][SLS];
    __shared__ __align__(16) float sR[CK][SRS];

    const int bh  = blockIdx.x;
    const int b   = bh / HH;
    const int h   = bh % HH;
    const int tid = threadIdx.x;

    const int dg = tid / 40;     // 0..5
    const int wg = tid % 40;     // 0..39
    const int d0 = dg * 8;
    const int w0 = wg * 8;

    const float* lb = left  + ((size_t)b * CC * HH + h) * WW;  // + c*HH*WW per channel
    const float* rb = right + ((size_t)b * CC * HH + h) * WW;

    float acc[8][8];
    #pragma unroll
    for (int di = 0; di < 8; di++)
        #pragma unroll
        for (int wi = 0; wi < 8; wi++)
            acc[di][wi] = 0.0f;

    // Precompute swizzled base indices (constants per thread).
    const int lw0 = SW(w0);                 // w0 % 32 in {0,8,16,24} -> +4 stays in block
    const int q   = w0 - d0 + (PAD - 8);    // logical right base, multiple of 8, >= 0
    const int rq0 = SW(q);
    const int rq1 = SW(q + 4);
    const int rq2 = SW(q + 8);
    const int rq3 = SW(q + 12);

    for (int c0 = 0; c0 < CC; c0 += CK) {
        __syncthreads();   // protect smem from previous iteration's readers

        // Stage CK channel rows of left & right (float4, coalesced, swizzled stores).
        #pragma unroll
        for (int i = tid; i < CK * (WW / 4); i += NT) {
            const int cc = i / (WW / 4);
            const int v  = (i % (WW / 4)) * 4;
            const size_t goff = (size_t)(c0 + cc) * (HH * WW) + v;
            const float4 lv = *(const float4*)(lb + goff);
            const float4 rv = *(const float4*)(rb + goff);
            *(float4*)&sL[cc][SW(v)]        = lv;
            *(float4*)&sR[cc][SW(PAD + v)]  = rv;
        }
        // Zero the pad region (PAD=48 floats = 12 float4 per row, CK*12 = 96 <= NT).
        if (tid < CK * (PAD / 4)) {
            const int cc = tid / (PAD / 4);
            const int v  = (tid % (PAD / 4)) * 4;
            *(float4*)&sR[cc][SW(v)] = make_float4(0.f, 0.f, 0.f, 0.f);
        }
        __syncthreads();

        #pragma unroll
        for (int cc = 0; cc < CK; cc++) {
            float l[8];
            *(float4*)&l[0] = *(const float4*)&sL[cc][lw0];
            *(float4*)&l[4] = *(const float4*)&sL[cc][lw0 + 4];

            // right logical indices q..q+15 cover w-d+PAD for w in [w0,w0+7],
            // d in [d0,d0+7]; r[k] = logical (q+k), need k = wi-di+8 in [1,15].
            float r[16];
            *(float4*)&r[0]  = *(const float4*)&sR[cc][rq0];
            *(float4*)&r[4]  = *(const float4*)&sR[cc][rq1];
            *(float4*)&r[8]  = *(const float4*)&sR[cc][rq2];
            *(float4*)&r[12] = *(const float4*)&sR[cc][rq3];

            #pragma unroll
            for (int di = 0; di < 8; di++)
                #pragma unroll
                for (int wi = 0; wi < 8; wi++)
                    acc[di][wi] = fmaf(l[wi], r[wi - di + 8], acc[di][wi]);
        }
    }

    const float inv = 1.0f / (float)CC;
    #pragma unroll
    for (int di = 0; di < 8; di++) {
        float* op = out + (((size_t)b * DD + (d0 + di)) * HH + h) * WW + w0;
        float4 o0 = make_float4(acc[di][0] * inv, acc[di][1] * inv,
                                acc[di][2] * inv, acc[di][3] * inv);
        float4 o1 = make_float4(acc[di][4] * inv, acc[di][5] * inv,
                                acc[di][6] * inv, acc[di][7] * inv);
        *(float4*)op       = o0;
        *(float4*)(op + 4) = o1;
    }
}

extern "C" void kernel_launch(void* const* d_in, const int* in_sizes, int n_in,
                              void* d_out, int out_size)
{
    const float* left  = (const float*)d_in[0];
    const float* right = (const float*)d_in[1];
    float* out = (float*)d_out;
    corvol_kernel<<<BB * HH, NT>>>(left, right, out);
}

// round 3
// speedup vs baseline: 2.1329x; 1.3736x over previous
#include <cuda_runtime.h>
#include <cstdint>

// Cost volume: out[b,d,h,w] = (1/C) * sum_c left[b,c,h,w] * right[b,c,h,w-d], 0 for w<d
// B=8, C=64, H=160, W=320, D=48.

#define BB 8
#define CC 64
#define HH 160
#define WW 320
#define DD 48

#define CK     8              // C-chunk per stage
#define NSTAGE (CC / CK)      // 8
#define PAD    48             // left zero-pad of right row (covers w-d down to -47)
#define NT     240            // 6 d-groups (x8d) * 40 w-groups (x8w)

// Bank-conflict-free arithmetic swizzle: +4-float gap every 32 floats.
#define SW(i) ((i) + 4 * ((i) >> 5))
#define SLS  356              // left  row physical floats (SW(316)+4)
#define SRS  412              // right row physical floats (SW(364)+4)
// smem: 2*8*(356+412)*4 = 49152 B = 48 KB exactly.

typedef unsigned long long ull;

__device__ __forceinline__ ull pk(float lo, float hi) {
    ull v; asm("mov.b64 %0, {%1, %2};" : "=l"(v) : "f"(lo), "f"(hi)); return v;
}
__device__ __forceinline__ void upk(ull v, float& lo, float& hi) {
    asm("mov.b64 {%0, %1}, %2;" : "=f"(lo), "=f"(hi) : "l"(v));
}
__device__ __forceinline__ void ffma2(ull& d, ull a, ull b) {
    asm("fma.rn.f32x2 %0, %1, %2, %0;" : "+l"(d) : "l"(a), "l"(b));
}
__device__ __forceinline__ void cpasync16(void* dst_smem, const void* src) {
    uint32_t d = (uint32_t)__cvta_generic_to_shared(dst_smem);
    asm volatile("cp.async.cg.shared.global [%0], [%1], 16;" :: "r"(d), "l"(src) : "memory");
}

__global__ __launch_bounds__(NT, 2) void corvol_kernel(
    const float* __restrict__ left,
    const float* __restrict__ right,
    float* __restrict__ out)
{
    __shared__ __align__(16) float sL[2][CK][SLS];
    __shared__ __align__(16) float sR[2][CK][SRS];

    const int bh  = blockIdx.x;
    const int b   = bh / HH;
    const int h   = bh % HH;
    const int tid = threadIdx.x;

    const int dg = tid / 40;       // 0..5
    const int wg = tid % 40;       // 0..39
    const int d0 = dg * 8;
    const int w0 = wg * 8;

    const float* lb = left  + ((size_t)b * CC * HH + h) * WW;
    const float* rb = right + ((size_t)b * CC * HH + h) * WW;

    // Zero the right-pad region ONCE for both buffers (data stores never touch it).
    // 2 bufs * 8 rows * 12 float4 = 192 items.
    if (tid < 2 * CK * (PAD / 4)) {
        const int buf = tid / (CK * (PAD / 4));
        const int cc  = (tid % (CK * (PAD / 4))) / (PAD / 4);
        const int v   = (tid % (PAD / 4)) * 4;
        *(float4*)&sR[buf][cc][SW(v)] = make_float4(0.f, 0.f, 0.f, 0.f);
    }

    ull acc2[8][4];
    #pragma unroll
    for (int di = 0; di < 8; di++)
        #pragma unroll
        for (int j = 0; j < 4; j++)
            acc2[di][j] = 0ull;

    const int lw0 = SW(w0);
    const int q   = w0 - d0 + (PAD - 8);   // logical right base (mult of 8, >= 0)
    const int rq0 = SW(q);
    const int rq1 = SW(q + 4);
    const int rq2 = SW(q + 8);
    const int rq3 = SW(q + 12);

    // ---- stage 0 copy ----
    #pragma unroll
    for (int i = tid; i < CK * (WW / 4); i += NT) {
        const int cc = i / (WW / 4);
        const int v  = (i % (WW / 4)) * 4;
        const size_t goff = (size_t)cc * (HH * WW) + v;
        cpasync16(&sL[0][cc][SW(v)],       lb + goff);
        cpasync16(&sR[0][cc][SW(PAD + v)], rb + goff);
    }
    asm volatile("cp.async.commit_group;" ::: "memory");

    for (int s = 0; s < NSTAGE; s++) {
        const int cur = s & 1;
        if (s + 1 < NSTAGE) {
            const int nxt = (s + 1) & 1;
            const int c0n = (s + 1) * CK;
            #pragma unroll
            for (int i = tid; i < CK * (WW / 4); i += NT) {
                const int cc = i / (WW / 4);
                const int v  = (i % (WW / 4)) * 4;
                const size_t goff = (size_t)(c0n + cc) * (HH * WW) + v;
                cpasync16(&sL[nxt][cc][SW(v)],       lb + goff);
                cpasync16(&sR[nxt][cc][SW(PAD + v)], rb + goff);
            }
            asm volatile("cp.async.commit_group;" ::: "memory");
            asm volatile("cp.async.wait_group 1;"  ::: "memory");
        } else {
            asm volatile("cp.async.wait_group 0;"  ::: "memory");
        }
        __syncthreads();   // stage s data visible to all

        #pragma unroll
        for (int cc = 0; cc < CK; cc++) {
            float l[8];
            *(float4*)&l[0] = *(const float4*)&sL[cur][cc][lw0];
            *(float4*)&l[4] = *(const float4*)&sL[cur][cc][lw0 + 4];
            float r[16];
            *(float4*)&r[0]  = *(const float4*)&sR[cur][cc][rq0];
            *(float4*)&r[4]  = *(const float4*)&sR[cur][cc][rq1];
            *(float4*)&r[8]  = *(const float4*)&sR[cur][cc][rq2];
            *(float4*)&r[12] = *(const float4*)&sR[cur][cc][rq3];

            ull l2[4];
            #pragma unroll
            for (int j = 0; j < 4; j++) l2[j] = pk(l[2 * j], l[2 * j + 1]);
            ull e[8];   // even-offset pairs (r[2k], r[2k+1]), k=1..7 used
            #pragma unroll
            for (int k = 1; k < 8; k++) e[k] = pk(r[2 * k], r[2 * k + 1]);
            ull o[7];   // odd-offset pairs (r[2m+1], r[2m+2])
            #pragma unroll
            for (int m = 0; m < 7; m++) o[m] = pk(r[2 * m + 1], r[2 * m + 2]);

            // acc2[di][j] covers (d0+di, w0+2j / w0+2j+1):
            //   needs pair starting at r[2j - di + 8]
            #pragma unroll
            for (int di = 0; di < 8; di++) {
                #pragma unroll
                for (int j = 0; j < 4; j++) {
                    const ull bop = (di & 1) ? o[j + (7 - di) / 2]
                                             : e[j + (8 - di) / 2];
                    ffma2(acc2[di][j], l2[j], bop);
                }
            }
        }
        __syncthreads();   // all reads of buf[cur] done before it is re-filled
    }

    const float inv = 1.0f / (float)CC;
    #pragma unroll
    for (int di = 0; di < 8; di++) {
        float v[8];
        #pragma unroll
        for (int j = 0; j < 4; j++) {
            float lo, hi;
            upk(acc2[di][j], lo, hi);
            v[2 * j]     = lo * inv;
            v[2 * j + 1] = hi * inv;
        }
        float* op = out + (((size_t)b * DD + (d0 + di)) * HH + h) * WW + w0;
        *(float4*)op       = make_float4(v[0], v[1], v[2], v[3]);
        *(float4*)(op + 4) = make_float4(v[4], v[5], v[6], v[7]);
    }
}

extern "C" void kernel_launch(void* const* d_in, const int* in_sizes, int n_in,
                              void* d_out, int out_size)
{
    const float* left  = (const float*)d_in[0];
    const float* right = (const float*)d_in[1];
    float* out = (float*)d_out;
    corvol_kernel<<<BB * HH, NT>>>(left, right, out);
}